// round 8
// baseline (speedup 1.0000x reference)
#include <cuda_runtime.h>
#include <math.h>
#include <float.h>

#define NBATCH 16
#define NANCH  5
#define NHH    96
#define NWW    96
#define MAXT   50
#define NCLS   40
#define CH     45
#define TSTR   53
#define NCELL  (NHH*NWW)                 // 9216
#define NALL   (NBATCH*NANCH*NCELL)      // 737280
#define NSLOT  (MAXT*NANCH)              // 250 per batch
#define CONF_GRID   720
#define CONF_BLOCK  256
#define CONF_THREADS (CONF_GRID*CONF_BLOCK)   // 184320; NALL/CONF_THREADS == 4 exactly

struct TRec { int cell; int best; int ign; int label; int correct; float tx, ty, tw, th; };

__device__ TRec  g_trec[NBATCH*MAXT];
__device__ int   g_slot[NBATCH*NSLOT];   // packed: cell|a<<14|wt<<17|type<<23 (0 = none)

__device__ float g_bceAll;
__device__ int   g_nCorrect, g_nProp;

__device__ __forceinline__ float softplusf(float x) {
    return fmaxf(x, 0.0f) + log1pf(expf(-fabsf(x)));
}

// ================= K1: init (block0/thread0; no concurrent writers) + per-target records =========
__global__ void k_targets(const float* __restrict__ pred,
                          const float* __restrict__ tgt,
                          const int*   __restrict__ ts) {
    if (blockIdx.x == 0 && threadIdx.x == 0) {
        g_bceAll = 0.f; g_nCorrect = 0; g_nProp = 0;
    }

    int warp = (blockIdx.x * blockDim.x + threadIdx.x) >> 5;
    int lane = threadIdx.x & 31;
    if (warp >= NBATCH * MAXT) return;
    int b = warp / MAXT, t = warp % MAXT;
    if (t >= ts[b]) return;                       // uniform across warp

    const float aw[NANCH] = {1.f, 2.f, 4.f, 2.f, 4.f};
    const float ah[NANCH] = {1.f, 2.f, 4.f, 4.f, 2.f};

    const float* row = tgt + (size_t)(b * MAXT + t) * TSTR;

    // label = first-argmax of row[13:53] (warp-parallel)
    float lv = -FLT_MAX; int li = NCLS;
    for (int c = lane; c < NCLS; c += 32) {
        float v = row[13 + c];
        if (v > lv) { lv = v; li = c; }
    }
    for (int off = 16; off; off >>= 1) {
        float ov = __shfl_down_sync(0xffffffffu, lv, off);
        int   oi = __shfl_down_sync(0xffffffffu, li, off);
        if (ov > lv || (ov == lv && oi < li)) { lv = ov; li = oi; }
    }
    int label = __shfl_sync(0xffffffffu, li, 0);

    float gx = row[0] * 0.0625f;
    float gy = row[1] * 0.0625f;
    float gh = row[3] * 0.0625f;
    float gw = row[4] * 0.0625f;
    int gi = (int)gx;
    int gj = (int)gy;

    float best_iou = -1.f; int best = 0; int ign = 0;
    #pragma unroll
    for (int a = 0; a < NANCH; a++) {
        float inter = fmaxf(fminf(gw, aw[a]) + 1.f, 0.f) * fmaxf(fminf(gh, ah[a]) + 1.f, 0.f);
        float denom = (gw + 1.f) * (gh + 1.f) + (aw[a] + 1.f) * (ah[a] + 1.f) - inter + 1e-16f;
        float iou = inter / denom;
        if (iou > best_iou) { best_iou = iou; best = a; }
        if (iou > 0.5f) ign |= (1 << a);
    }

    const float* p = pred + (size_t)(((b * NANCH + best) * NHH + gj) * NWW + gi) * CH;
    float cv = -FLT_MAX; int ci = NCLS;
    for (int c = lane; c < NCLS; c += 32) {
        float v = p[5 + c];
        if (v > cv) { cv = v; ci = c; }
    }
    for (int off = 16; off; off >>= 1) {
        float ov = __shfl_down_sync(0xffffffffu, cv, off);
        int   oi = __shfl_down_sync(0xffffffffu, ci, off);
        if (ov > cv || (ov == cv && oi < ci)) { cv = ov; ci = oi; }
    }

    if (lane == 0) {
        float pc = p[0], px = p[1], py = p[2], ph = p[3], pw = p[4];
        float pbx = px + (float)gi;
        float pby = py + (float)gj;
        float pbw = expf(pw) * aw[best];
        float pbh = expf(ph) * ah[best];

        float gx1 = gx - gw * 0.5f, gx2 = gx + gw * 0.5f;
        float gy1 = gy - gh * 0.5f, gy2 = gy + gh * 0.5f;
        float px1 = pbx - pbw * 0.5f, px2 = pbx + pbw * 0.5f;
        float py1 = pby - pbh * 0.5f, py2 = pby + pbh * 0.5f;
        float iw = fmaxf(fminf(gx2, px2) - fmaxf(gx1, px1) + 1.f, 0.f);
        float ih = fmaxf(fminf(gy2, py2) - fmaxf(gy1, py1) + 1.f, 0.f);
        float inter = iw * ih;
        float ga = (gx2 - gx1 + 1.f) * (gy2 - gy1 + 1.f);
        float pa = (px2 - px1 + 1.f) * (py2 - py1 + 1.f);
        float iou = inter / (ga + pa - inter + 1e-16f);

        TRec r;
        r.cell = gj * NWW + gi;
        r.best = best;
        r.ign  = ign;
        r.label = label;
        r.correct = (iou > 0.5f && ci == label && pc > 0.5f) ? 1 : 0;
        r.tx = gx - (float)gi;
        r.ty = gy - (float)gj;
        r.tw = logf(gw / aw[best] + 1e-16f);
        r.th = logf(gh / ah[best] + 1e-16f);
        g_trec[warp] = r;
    }
}

// ================= K2: conf reduction (all blocks) + per-batch resolve (blocks < 16) =========
// VERBATIM R6 structure — 18 regs, occ ~94%, DRAM-saturating.
__global__ void __launch_bounds__(CONF_BLOCK) k_resolveconf(const float* __restrict__ pred,
                                                            const int*   __restrict__ ts) {
    // ---- conf plane: exactly 4 elements per thread, independent loads ----
    {
        int tid = blockIdx.x * blockDim.x + threadIdx.x;   // 0 .. 184319
        float s = 0.f; int c = 0;
        #pragma unroll
        for (int k = 0; k < 4; k++) {
            const float* ap = pred + (size_t)(tid + k * CONF_THREADS) * CH;
            float pc;
            asm volatile("ld.global.nc.L2::64B.f32 %0, [%1];" : "=f"(pc) : "l"(ap));
            s += softplusf(pc);
            c += (pc > 0.f);
        }
        for (int off = 16; off; off >>= 1) {
            s += __shfl_down_sync(0xffffffffu, s, off);
            c += __shfl_down_sync(0xffffffffu, c, off);
        }
        __shared__ float ws[8]; __shared__ int wc[8];
        int lane = threadIdx.x & 31, wid = threadIdx.x >> 5;
        if (lane == 0) { ws[wid] = s; wc[wid] = c; }
        __syncthreads();
        if (wid == 0) {
            s = (lane < 8) ? ws[lane] : 0.f;
            c = (lane < 8) ? wc[lane] : 0;
            for (int off = 4; off; off >>= 1) {
                s += __shfl_down_sync(0xffffffffu, s, off);
                c += __shfl_down_sync(0xffffffffu, c, off);
            }
            if (lane == 0) { atomicAdd(&g_bceAll, s); atomicAdd(&g_nProp, c); }
        }
    }

    // ---- resolve: block-uniform branch, verbatim R5/R6 logic + nCorrect from flags ----
    if (blockIdx.x < NBATCH) {
        int b = blockIdx.x;
        int n = ts[b];
        __shared__ int sc[MAXT], sb[MAXT], si[MAXT];

        for (int t = threadIdx.x; t < n; t += blockDim.x) {
            TRec r = g_trec[b * MAXT + t];
            sc[t] = r.cell; sb[t] = r.best; si[t] = r.ign;
            if (r.correct) atomicAdd(&g_nCorrect, 1);
        }
        __syncthreads();

        int s = threadIdx.x;              // (t, a) pair index
        if (s < NSLOT) {
            int out = 0;
            int t = s / NANCH, a = s % NANCH;
            if (t < n) {
                int mycell = sc[t];
                bool firstOcc = true;
                for (int u = 0; u < t; u++) if (sc[u] == mycell) { firstOcc = false; break; }
                if (firstOcc) {
                    int Bv = -1, Iv = -1;
                    for (int u = 0; u < n; u++) {
                        if (sc[u] == mycell) {
                            if ((si[u] >> a) & 1) Iv = u;
                            if (sb[u] == a)       Bv = u;
                        }
                    }
                    int type;
                    if (Bv < 0) type = (Iv < 0) ? 0 : 1;      // 1: cmf==0 (ignored, not best)
                    else        type = (Iv <= Bv) ? 2 : 3;     // 2: winner; 3: mask=1,conf=0
                    if (type)
                        out = mycell | (a << 14) | ((type == 2 ? Bv : 0) << 17) | (type << 23);
                }
            }
            g_slot[b * NSLOT + s] = out;
        }
    }
}

// ================= K3: single-block slots + finalize (smem accumulators, no global tail) =========
__global__ void __launch_bounds__(1024) k_slotsfinal(const float* __restrict__ pred,
                                                     const int*   __restrict__ ts,
                                                     float* __restrict__ out, int out_size) {
    __shared__ float sSx, sSy, sSw, sSh, sSce, sMaskB, sCorrB, sSubPc;
    __shared__ int   sCorrC, sNM;
    if (threadIdx.x == 0) {
        sSx = sSy = sSw = sSh = sSce = sMaskB = sCorrB = sSubPc = 0.f;
        sCorrC = 0; sNM = 0;
    }
    __syncthreads();

    for (int s = threadIdx.x; s < NBATCH * NSLOT; s += blockDim.x) {
        int v = g_slot[s];
        if (!v) continue;
        int b    = s / NSLOT;
        int cell = v & 0x3FFF;
        int a    = (v >> 14) & 7;
        int wt   = (v >> 17) & 63;
        int type = (v >> 23) & 3;

        const float* p = pred + (size_t)((b * NANCH + a) * NCELL + cell) * CH;
        float pc = p[0];
        float sp = softplusf(pc);

        if (type == 3) { atomicAdd(&sSubPc, pc); continue; }  // cmf=1, tconf=1
        atomicAdd(&sCorrB, sp);                                // cmf==0 slot
        atomicAdd(&sCorrC, 1);
        if (type == 1) continue;

        // winner (mask=1, tconf=1)
        atomicAdd(&sMaskB, sp - pc);
        atomicAdd(&sNM, 1);
        TRec r = g_trec[b * MAXT + wt];
        float dx = p[1] - r.tx, dy = p[2] - r.ty;
        float dh = p[3] - r.th, dw = p[4] - r.tw;
        atomicAdd(&sSx, dx * dx);
        atomicAdd(&sSy, dy * dy);
        atomicAdd(&sSw, dw * dw);
        atomicAdd(&sSh, dh * dh);

        float mx = -FLT_MAX;
        #pragma unroll
        for (int c = 0; c < NCLS; c++) mx = fmaxf(mx, p[5 + c]);
        float se = 0.f;
        #pragma unroll
        for (int c = 0; c < NCLS; c++) se += expf(p[5 + c] - mx);
        atomicAdd(&sSce, mx + logf(se) - p[5 + r.label]);
    }
    __syncthreads();

    if (threadIdx.x == 0) {
        int nGT = 0;
        for (int b = 0; b < NBATCH; b++) nGT += ts[b];
        float nM = (float)sNM;
        float lx = sSx / nM, ly = sSy / nM, lw = sSw / nM, lh = sSh / nM;
        float cmfB = g_bceAll - sCorrB - sSubPc;
        float cmfC = (float)(NALL - sCorrC);
        float lconf = cmfB / cmfC + sMaskB / nM;
        float lcls  = (1.0f / NBATCH) * sSce / nM;
        float coord = lx + ly + lw + lh;
        float loss  = coord + lconf + lcls;
        float nCor  = (float)g_nCorrect;
        int   gtd   = nGT > 1 ? nGT : 1;
        float recall = nCor / (float)gtd;
        float nProp = (float)g_nProp;
        float prec  = (nProp > 0.f) ? (nCor / fmaxf(nProp, 1.f)) : 1.f;
        if (out_size >= 6) {
            out[0] = loss; out[1] = coord; out[2] = lconf;
            out[3] = lcls; out[4] = recall; out[5] = prec;
        }
    }
}

extern "C" void kernel_launch(void* const* d_in, const int* in_sizes, int n_in,
                              void* d_out, int out_size) {
    const float* pred = (const float*)d_in[0];
    const float* tgt  = (const float*)d_in[1];
    const int*   ts   = (const int*)d_in[2];
    float* out = (float*)d_out;

    k_targets<<<(NBATCH * MAXT * 32 + 255) / 256, 256>>>(pred, tgt, ts);
    k_resolveconf<<<CONF_GRID, CONF_BLOCK>>>(pred, ts);
    k_slotsfinal<<<1, 1024>>>(pred, ts, out, out_size);
}

// round 9
// speedup vs baseline: 1.7401x; 1.7401x over previous
#include <cuda_runtime.h>
#include <math.h>
#include <float.h>

#define NBATCH 16
#define NANCH  5
#define NHH    96
#define NWW    96
#define MAXT   50
#define NCLS   40
#define CH     45
#define TSTR   53
#define NCELL  (NHH*NWW)                 // 9216
#define NALL   (NBATCH*NANCH*NCELL)      // 737280
#define NSLOT  (MAXT*NANCH)              // 250 per batch
#define CONF_GRID   720
#define CONF_BLOCK  256
#define CONF_THREADS (CONF_GRID*CONF_BLOCK)   // 184320; NALL/CONF_THREADS == 4 exactly

struct TRec { int label; float tx, ty, tw, th; };

__device__ TRec  g_trec[NBATCH*MAXT];
__device__ int   g_slot[NBATCH*NSLOT];   // packed: cell|a<<14|wt<<17|type<<23 (0 = none)
__device__ float g_confPart[CONF_GRID];  // overwritten every run — no init needed
__device__ int   g_propPart[CONF_GRID];
__device__ int   g_ncPart[NBATCH];

__device__ __forceinline__ float softplusf(float x) {
    return fmaxf(x, 0.0f) + log1pf(expf(-fabsf(x)));
}

// ================= K1: conf partials (all blocks) + targets/resolve (blocks 0..15) =========
__global__ void __launch_bounds__(CONF_BLOCK, 8) k_mega(const float* __restrict__ pred,
                                                        const float* __restrict__ tgt,
                                                        const int*   __restrict__ ts) {
    // ---- conf plane: exactly 4 elements per thread, independent loads, per-block partial ----
    {
        int tid = blockIdx.x * blockDim.x + threadIdx.x;   // 0 .. 184319
        float s = 0.f; int c = 0;
        #pragma unroll
        for (int k = 0; k < 4; k++) {
            const float* ap = pred + (size_t)(tid + k * CONF_THREADS) * CH;
            float pc;
            asm volatile("ld.global.nc.L2::64B.f32 %0, [%1];" : "=f"(pc) : "l"(ap));
            s += softplusf(pc);
            c += (pc > 0.f);
        }
        for (int off = 16; off; off >>= 1) {
            s += __shfl_down_sync(0xffffffffu, s, off);
            c += __shfl_down_sync(0xffffffffu, c, off);
        }
        __shared__ float ws[8]; __shared__ int wc[8];
        int lane = threadIdx.x & 31, wid = threadIdx.x >> 5;
        if (lane == 0) { ws[wid] = s; wc[wid] = c; }
        __syncthreads();
        if (wid == 0) {
            s = (lane < 8) ? ws[lane] : 0.f;
            c = (lane < 8) ? wc[lane] : 0;
            for (int off = 4; off; off >>= 1) {
                s += __shfl_down_sync(0xffffffffu, s, off);
                c += __shfl_down_sync(0xffffffffu, c, off);
            }
            if (lane == 0) { g_confPart[blockIdx.x] = s; g_propPart[blockIdx.x] = c; }
        }
    }

    // ---- fat path: block b < 16 handles batch b entirely ----
    if (blockIdx.x < NBATCH) {
        int b = blockIdx.x;
        int n = ts[b];
        __shared__ int sc[MAXT], sb[MAXT], si[MAXT];
        __shared__ int s_nc;
        if (threadIdx.x == 0) s_nc = 0;
        __syncthreads();

        // thread-per-target record computation (serial first-argmax == reference tie rule)
        int t = threadIdx.x;
        if (t < n) {
            const float aw[NANCH] = {1.f, 2.f, 4.f, 2.f, 4.f};
            const float ah[NANCH] = {1.f, 2.f, 4.f, 4.f, 2.f};
            const float* row = tgt + (size_t)(b * MAXT + t) * TSTR;

            float lv = -FLT_MAX; int label = 0;
            #pragma unroll
            for (int c = 0; c < NCLS; c++) {
                float v = row[13 + c];
                if (v > lv) { lv = v; label = c; }
            }

            float gx = row[0] * 0.0625f;
            float gy = row[1] * 0.0625f;
            float gh = row[3] * 0.0625f;
            float gw = row[4] * 0.0625f;
            int gi = (int)gx;
            int gj = (int)gy;

            float best_iou = -1.f; int best = 0; int ign = 0;
            #pragma unroll
            for (int a = 0; a < NANCH; a++) {
                float inter = fmaxf(fminf(gw, aw[a]) + 1.f, 0.f) * fmaxf(fminf(gh, ah[a]) + 1.f, 0.f);
                float denom = (gw + 1.f) * (gh + 1.f) + (aw[a] + 1.f) * (ah[a] + 1.f) - inter + 1e-16f;
                float iou = inter / denom;
                if (iou > best_iou) { best_iou = iou; best = a; }
                if (iou > 0.5f) ign |= (1 << a);
            }

            const float* p = pred + (size_t)(((b * NANCH + best) * NHH + gj) * NWW + gi) * CH;
            float cv = -FLT_MAX; int ci = 0;
            #pragma unroll
            for (int c = 0; c < NCLS; c++) {
                float v = p[5 + c];
                if (v > cv) { cv = v; ci = c; }
            }

            float pc = p[0], px = p[1], py = p[2], ph = p[3], pw = p[4];
            float pbx = px + (float)gi;
            float pby = py + (float)gj;
            float pbw = expf(pw) * aw[best];
            float pbh = expf(ph) * ah[best];

            float gx1 = gx - gw * 0.5f, gx2 = gx + gw * 0.5f;
            float gy1 = gy - gh * 0.5f, gy2 = gy + gh * 0.5f;
            float px1 = pbx - pbw * 0.5f, px2 = pbx + pbw * 0.5f;
            float py1 = pby - pbh * 0.5f, py2 = pby + pbh * 0.5f;
            float iw = fmaxf(fminf(gx2, px2) - fmaxf(gx1, px1) + 1.f, 0.f);
            float ih = fmaxf(fminf(gy2, py2) - fmaxf(gy1, py1) + 1.f, 0.f);
            float inter = iw * ih;
            float ga = (gx2 - gx1 + 1.f) * (gy2 - gy1 + 1.f);
            float pa = (px2 - px1 + 1.f) * (py2 - py1 + 1.f);
            float iou = inter / (ga + pa - inter + 1e-16f);

            if (iou > 0.5f && ci == label && pc > 0.5f) atomicAdd(&s_nc, 1);

            sc[t] = gj * NWW + gi;
            sb[t] = best;
            si[t] = ign;
            TRec r;
            r.label = label;
            r.tx = gx - (float)gi;
            r.ty = gy - (float)gj;
            r.tw = logf(gw / aw[best] + 1e-16f);
            r.th = logf(gh / ah[best] + 1e-16f);
            g_trec[b * MAXT + t] = r;
        }
        __syncthreads();

        // resolve (verbatim R5/R6 logic)
        int s = threadIdx.x;              // (t, a) pair index
        if (s < NSLOT) {
            int out = 0;
            int tt = s / NANCH, a = s % NANCH;
            if (tt < n) {
                int mycell = sc[tt];
                bool firstOcc = true;
                for (int u = 0; u < tt; u++) if (sc[u] == mycell) { firstOcc = false; break; }
                if (firstOcc) {
                    int Bv = -1, Iv = -1;
                    for (int u = 0; u < n; u++) {
                        if (sc[u] == mycell) {
                            if ((si[u] >> a) & 1) Iv = u;
                            if (sb[u] == a)       Bv = u;
                        }
                    }
                    int type;
                    if (Bv < 0) type = (Iv < 0) ? 0 : 1;      // 1: cmf==0 (ignored, not best)
                    else        type = (Iv <= Bv) ? 2 : 3;     // 2: winner; 3: mask=1,conf=0
                    if (type)
                        out = mycell | (a << 14) | ((type == 2 ? Bv : 0) << 17) | (type << 23);
                }
            }
            g_slot[b * NSLOT + s] = out;
        }
        if (threadIdx.x == 0) g_ncPart[b] = s_nc;
    }
}

// ================= K2: tail — slots + finalize, register accumulation (1 block) =========
__global__ void __launch_bounds__(1024) k_tail(const float* __restrict__ pred,
                                               const int*   __restrict__ ts,
                                               float* __restrict__ out, int out_size) {
    int tid = threadIdx.x;

    // fv: 0=Sx 1=Sy 2=Sw 3=Sh 4=Sce 5=maskB 6=corrB 7=subPc 8=bceAll
    float fv[9] = {0.f,0.f,0.f,0.f,0.f,0.f,0.f,0.f,0.f};
    // iv: 0=corrCnt 1=nM 2=nProp 3=nCorrect
    int   iv[4] = {0,0,0,0};

    for (int i = tid; i < CONF_GRID; i += 1024) {
        fv[8] += g_confPart[i];
        iv[2] += g_propPart[i];
    }
    if (tid < NBATCH) iv[3] = g_ncPart[tid];

    for (int s = tid; s < NBATCH * NSLOT; s += 1024) {
        int v = g_slot[s];
        if (!v) continue;
        int b    = s / NSLOT;
        int cell = v & 0x3FFF;
        int a    = (v >> 14) & 7;
        int wt   = (v >> 17) & 63;
        int type = (v >> 23) & 3;

        const float* p = pred + (size_t)((b * NANCH + a) * NCELL + cell) * CH;
        float pc = p[0];
        float sp = softplusf(pc);

        if (type == 3) { fv[7] += pc; continue; }   // cmf=1, tconf=1
        fv[6] += sp;                                 // cmf==0 slot
        iv[0] += 1;
        if (type == 1) continue;

        // winner (mask=1, tconf=1)
        fv[5] += sp - pc;
        iv[1] += 1;
        TRec r = g_trec[b * MAXT + wt];
        float dx = p[1] - r.tx, dy = p[2] - r.ty;
        float dh = p[3] - r.th, dw = p[4] - r.tw;
        fv[0] += dx * dx;
        fv[1] += dy * dy;
        fv[2] += dw * dw;
        fv[3] += dh * dh;

        float mx = -FLT_MAX;
        #pragma unroll
        for (int c = 0; c < NCLS; c++) mx = fmaxf(mx, p[5 + c]);
        float se = 0.f;
        #pragma unroll
        for (int c = 0; c < NCLS; c++) se += expf(p[5 + c] - mx);
        fv[4] += mx + logf(se) - p[5 + r.label];
    }

    // intra-warp reduce
    #pragma unroll
    for (int off = 16; off; off >>= 1) {
        #pragma unroll
        for (int q = 0; q < 9; q++) fv[q] += __shfl_down_sync(0xffffffffu, fv[q], off);
        #pragma unroll
        for (int q = 0; q < 4; q++) iv[q] += __shfl_down_sync(0xffffffffu, iv[q], off);
    }

    __shared__ float sf[9][32];
    __shared__ int   si2[4][32];
    int lane = tid & 31, wid = tid >> 5;
    if (lane == 0) {
        #pragma unroll
        for (int q = 0; q < 9; q++) sf[q][wid] = fv[q];
        #pragma unroll
        for (int q = 0; q < 4; q++) si2[q][wid] = iv[q];
    }
    __syncthreads();
    if (wid == 0) {
        #pragma unroll
        for (int q = 0; q < 9; q++) fv[q] = sf[q][lane];
        #pragma unroll
        for (int q = 0; q < 4; q++) iv[q] = si2[q][lane];
        #pragma unroll
        for (int off = 16; off; off >>= 1) {
            #pragma unroll
            for (int q = 0; q < 9; q++) fv[q] += __shfl_down_sync(0xffffffffu, fv[q], off);
            #pragma unroll
            for (int q = 0; q < 4; q++) iv[q] += __shfl_down_sync(0xffffffffu, iv[q], off);
        }
        if (lane == 0) {
            int nGT = 0;
            for (int b = 0; b < NBATCH; b++) nGT += ts[b];
            float nM = (float)iv[1];
            float lx = fv[0] / nM, ly = fv[1] / nM, lw = fv[2] / nM, lh = fv[3] / nM;
            float coord = lx + ly + lw + lh;
            float cmfB = fv[8] - fv[6] - fv[7];
            float cmfC = (float)(NALL - iv[0]);
            float lconf = cmfB / cmfC + fv[5] / nM;
            float lcls  = (1.0f / NBATCH) * fv[4] / nM;
            float loss  = coord + lconf + lcls;
            float nCor  = (float)iv[3];
            int   gtd   = nGT > 1 ? nGT : 1;
            float recall = nCor / (float)gtd;
            float nProp = (float)iv[2];
            float prec  = (nProp > 0.f) ? (nCor / fmaxf(nProp, 1.f)) : 1.f;
            if (out_size >= 6) {
                out[0] = loss; out[1] = coord; out[2] = lconf;
                out[3] = lcls; out[4] = recall; out[5] = prec;
            }
        }
    }
}

extern "C" void kernel_launch(void* const* d_in, const int* in_sizes, int n_in,
                              void* d_out, int out_size) {
    const float* pred = (const float*)d_in[0];
    const float* tgt  = (const float*)d_in[1];
    const int*   ts   = (const int*)d_in[2];
    float* out = (float*)d_out;

    k_mega<<<CONF_GRID, CONF_BLOCK>>>(pred, tgt, ts);
    k_tail<<<1, 1024>>>(pred, ts, out, out_size);
}

// round 10
// speedup vs baseline: 2.3061x; 1.3253x over previous
#include <cuda_runtime.h>
#include <math.h>
#include <float.h>

#define NBATCH 16
#define NANCH  5
#define NHH    96
#define NWW    96
#define MAXT   50
#define NCLS   40
#define CH     45
#define TSTR   53
#define NCELL  (NHH*NWW)                 // 9216
#define NALL   (NBATCH*NANCH*NCELL)      // 737280
#define NSLOT  (MAXT*NANCH)              // 250 per batch
#define CONF_GRID   720
#define CONF_BLOCK  256
#define CONF_THREADS (CONF_GRID*CONF_BLOCK)   // 184320; NALL/CONF_THREADS == 4 exactly
#define TAIL_GRID   32
#define TAIL_BLOCK  128
#define NFQ 9   // Sx Sy Sw Sh Sce maskB corrB subPc bceAll
#define NIQ 5   // corrCnt nM nProp nCorrect nGT

struct TRec { int label; float tx, ty, tw, th; };

__device__ TRec  g_trec[NBATCH*MAXT];
__device__ int   g_slot[NBATCH*NSLOT];   // packed: cell|a<<14|wt<<17|type<<23 (0 = none)
__device__ float g_confPart[CONF_GRID];  // overwritten every run — no init needed
__device__ int   g_propPart[CONF_GRID];
__device__ int   g_ncPart[NBATCH];
__device__ float g_bpF[NFQ][TAIL_GRID];  // K2 block partials (overwritten every run)
__device__ int   g_bpI[NIQ][TAIL_GRID];
__device__ int   g_done2;

__device__ __forceinline__ float softplusf(float x) {
    return fmaxf(x, 0.0f) + log1pf(expf(-fabsf(x)));
}

// ================= K1: conf partials (all blocks) + targets/resolve (blocks 0..15) =========
// VERBATIM R9 k_mega (measured ~12.7 us) + g_done2 reset in init.
__global__ void __launch_bounds__(CONF_BLOCK, 8) k_mega(const float* __restrict__ pred,
                                                        const float* __restrict__ tgt,
                                                        const int*   __restrict__ ts) {
    if (blockIdx.x == 0 && threadIdx.x == 0) g_done2 = 0;

    // ---- conf plane: exactly 4 elements per thread, independent loads, per-block partial ----
    {
        int tid = blockIdx.x * blockDim.x + threadIdx.x;   // 0 .. 184319
        float s = 0.f; int c = 0;
        #pragma unroll
        for (int k = 0; k < 4; k++) {
            const float* ap = pred + (size_t)(tid + k * CONF_THREADS) * CH;
            float pc;
            asm volatile("ld.global.nc.L2::64B.f32 %0, [%1];" : "=f"(pc) : "l"(ap));
            s += softplusf(pc);
            c += (pc > 0.f);
        }
        for (int off = 16; off; off >>= 1) {
            s += __shfl_down_sync(0xffffffffu, s, off);
            c += __shfl_down_sync(0xffffffffu, c, off);
        }
        __shared__ float ws[8]; __shared__ int wc[8];
        int lane = threadIdx.x & 31, wid = threadIdx.x >> 5;
        if (lane == 0) { ws[wid] = s; wc[wid] = c; }
        __syncthreads();
        if (wid == 0) {
            s = (lane < 8) ? ws[lane] : 0.f;
            c = (lane < 8) ? wc[lane] : 0;
            for (int off = 4; off; off >>= 1) {
                s += __shfl_down_sync(0xffffffffu, s, off);
                c += __shfl_down_sync(0xffffffffu, c, off);
            }
            if (lane == 0) { g_confPart[blockIdx.x] = s; g_propPart[blockIdx.x] = c; }
        }
    }

    // ---- fat path: block b < 16 handles batch b entirely ----
    if (blockIdx.x < NBATCH) {
        int b = blockIdx.x;
        int n = ts[b];
        __shared__ int sc[MAXT], sb[MAXT], si[MAXT];
        __shared__ int s_nc;
        if (threadIdx.x == 0) s_nc = 0;
        __syncthreads();

        int t = threadIdx.x;
        if (t < n) {
            const float aw[NANCH] = {1.f, 2.f, 4.f, 2.f, 4.f};
            const float ah[NANCH] = {1.f, 2.f, 4.f, 4.f, 2.f};
            const float* row = tgt + (size_t)(b * MAXT + t) * TSTR;

            float lv = -FLT_MAX; int label = 0;
            #pragma unroll
            for (int c = 0; c < NCLS; c++) {
                float v = row[13 + c];
                if (v > lv) { lv = v; label = c; }
            }

            float gx = row[0] * 0.0625f;
            float gy = row[1] * 0.0625f;
            float gh = row[3] * 0.0625f;
            float gw = row[4] * 0.0625f;
            int gi = (int)gx;
            int gj = (int)gy;

            float best_iou = -1.f; int best = 0; int ign = 0;
            #pragma unroll
            for (int a = 0; a < NANCH; a++) {
                float inter = fmaxf(fminf(gw, aw[a]) + 1.f, 0.f) * fmaxf(fminf(gh, ah[a]) + 1.f, 0.f);
                float denom = (gw + 1.f) * (gh + 1.f) + (aw[a] + 1.f) * (ah[a] + 1.f) - inter + 1e-16f;
                float iou = inter / denom;
                if (iou > best_iou) { best_iou = iou; best = a; }
                if (iou > 0.5f) ign |= (1 << a);
            }

            const float* p = pred + (size_t)(((b * NANCH + best) * NHH + gj) * NWW + gi) * CH;
            float cv = -FLT_MAX; int ci = 0;
            #pragma unroll
            for (int c = 0; c < NCLS; c++) {
                float v = p[5 + c];
                if (v > cv) { cv = v; ci = c; }
            }

            float pc = p[0], px = p[1], py = p[2], ph = p[3], pw = p[4];
            float pbx = px + (float)gi;
            float pby = py + (float)gj;
            float pbw = expf(pw) * aw[best];
            float pbh = expf(ph) * ah[best];

            float gx1 = gx - gw * 0.5f, gx2 = gx + gw * 0.5f;
            float gy1 = gy - gh * 0.5f, gy2 = gy + gh * 0.5f;
            float px1 = pbx - pbw * 0.5f, px2 = pbx + pbw * 0.5f;
            float py1 = pby - pbh * 0.5f, py2 = pby + pbh * 0.5f;
            float iw = fmaxf(fminf(gx2, px2) - fmaxf(gx1, px1) + 1.f, 0.f);
            float ih = fmaxf(fminf(gy2, py2) - fmaxf(gy1, py1) + 1.f, 0.f);
            float inter = iw * ih;
            float ga = (gx2 - gx1 + 1.f) * (gy2 - gy1 + 1.f);
            float pa = (px2 - px1 + 1.f) * (py2 - py1 + 1.f);
            float iou = inter / (ga + pa - inter + 1e-16f);

            if (iou > 0.5f && ci == label && pc > 0.5f) atomicAdd(&s_nc, 1);

            sc[t] = gj * NWW + gi;
            sb[t] = best;
            si[t] = ign;
            TRec r;
            r.label = label;
            r.tx = gx - (float)gi;
            r.ty = gy - (float)gj;
            r.tw = logf(gw / aw[best] + 1e-16f);
            r.th = logf(gh / ah[best] + 1e-16f);
            g_trec[b * MAXT + t] = r;
        }
        __syncthreads();

        int s = threadIdx.x;              // (t, a) pair index
        if (s < NSLOT) {
            int out = 0;
            int tt = s / NANCH, a = s % NANCH;
            if (tt < n) {
                int mycell = sc[tt];
                bool firstOcc = true;
                for (int u = 0; u < tt; u++) if (sc[u] == mycell) { firstOcc = false; break; }
                if (firstOcc) {
                    int Bv = -1, Iv = -1;
                    for (int u = 0; u < n; u++) {
                        if (sc[u] == mycell) {
                            if ((si[u] >> a) & 1) Iv = u;
                            if (sb[u] == a)       Bv = u;
                        }
                    }
                    int type;
                    if (Bv < 0) type = (Iv < 0) ? 0 : 1;      // 1: cmf==0 (ignored, not best)
                    else        type = (Iv <= Bv) ? 2 : 3;     // 2: winner; 3: mask=1,conf=0
                    if (type)
                        out = mycell | (a << 14) | ((type == 2 ? Bv : 0) << 17) | (type << 23);
                }
            }
            g_slot[b * NSLOT + s] = out;
        }
        if (threadIdx.x == 0) g_ncPart[b] = s_nc;
    }
}

// ================= K2: slots across 32 SMs + last-block finalize =========
__global__ void __launch_bounds__(TAIL_BLOCK) k_tail(const float* __restrict__ pred,
                                                     const int*   __restrict__ ts,
                                                     float* __restrict__ out, int out_size) {
    int tid = threadIdx.x;
    int gthread = blockIdx.x * TAIL_BLOCK + tid;   // 0..4095

    float fv[NFQ] = {0.f,0.f,0.f,0.f,0.f,0.f,0.f,0.f,0.f};
    int   iv[NIQ] = {0,0,0,0,0};

    // fold conf partials, nc partials, ts (each entry claimed by exactly one global thread)
    if (gthread < CONF_GRID) { fv[8] = g_confPart[gthread]; iv[2] = g_propPart[gthread]; }
    if (gthread < NBATCH)    { iv[3] = g_ncPart[gthread];   iv[4] = ts[gthread]; }

    // one slot per global thread
    if (gthread < NBATCH * NSLOT) {
        int v = g_slot[gthread];
        if (v) {
            int b    = gthread / NSLOT;
            int cell = v & 0x3FFF;
            int a    = (v >> 14) & 7;
            int wt   = (v >> 17) & 63;
            int type = (v >> 23) & 3;

            const float* p = pred + (size_t)((b * NANCH + a) * NCELL + cell) * CH;
            float pc = p[0];
            float sp = softplusf(pc);

            if (type == 3) {
                fv[7] += pc;                    // cmf=1, tconf=1
            } else {
                fv[6] += sp;                    // cmf==0 slot
                iv[0] += 1;
                if (type == 2) {
                    // winner (mask=1, tconf=1)
                    fv[5] += sp - pc;
                    iv[1] += 1;
                    TRec r = g_trec[b * MAXT + wt];
                    float dx = p[1] - r.tx, dy = p[2] - r.ty;
                    float dh = p[3] - r.th, dw = p[4] - r.tw;
                    fv[0] += dx * dx;
                    fv[1] += dy * dy;
                    fv[2] += dw * dw;
                    fv[3] += dh * dh;

                    float mx = -FLT_MAX;
                    #pragma unroll
                    for (int c = 0; c < NCLS; c++) mx = fmaxf(mx, p[5 + c]);
                    float se = 0.f;
                    #pragma unroll
                    for (int c = 0; c < NCLS; c++) se += __expf(p[5 + c] - mx);
                    fv[4] += mx + __logf(se) - p[5 + r.label];
                }
            }
        }
    }

    // block register reduce: warp shuffle then cross-warp smem (4 warps)
    #pragma unroll
    for (int off = 16; off; off >>= 1) {
        #pragma unroll
        for (int q = 0; q < NFQ; q++) fv[q] += __shfl_down_sync(0xffffffffu, fv[q], off);
        #pragma unroll
        for (int q = 0; q < NIQ; q++) iv[q] += __shfl_down_sync(0xffffffffu, iv[q], off);
    }
    __shared__ float sf[NFQ][4];
    __shared__ int   si2[NIQ][4];
    int lane = tid & 31, wid = tid >> 5;
    if (lane == 0) {
        #pragma unroll
        for (int q = 0; q < NFQ; q++) sf[q][wid] = fv[q];
        #pragma unroll
        for (int q = 0; q < NIQ; q++) si2[q][wid] = iv[q];
    }
    __syncthreads();
    if (tid == 0) {
        #pragma unroll
        for (int q = 0; q < NFQ; q++)
            g_bpF[q][blockIdx.x] = sf[q][0] + sf[q][1] + sf[q][2] + sf[q][3];
        #pragma unroll
        for (int q = 0; q < NIQ; q++)
            g_bpI[q][blockIdx.x] = si2[q][0] + si2[q][1] + si2[q][2] + si2[q][3];
    }

    // last-block ticket
    __syncthreads();
    __shared__ int isLast;
    if (tid == 0) {
        __threadfence();
        isLast = (atomicAdd(&g_done2, 1) == TAIL_GRID - 1) ? 1 : 0;
    }
    __syncthreads();
    if (!isLast || wid != 0) return;

    // warp 0 of last block: lane l loads block-l partials (independent loads), reduce
    __threadfence();
    float ff[NFQ]; int ii[NIQ];
    #pragma unroll
    for (int q = 0; q < NFQ; q++) ff[q] = g_bpF[q][lane];
    #pragma unroll
    for (int q = 0; q < NIQ; q++) ii[q] = g_bpI[q][lane];
    #pragma unroll
    for (int off = 16; off; off >>= 1) {
        #pragma unroll
        for (int q = 0; q < NFQ; q++) ff[q] += __shfl_down_sync(0xffffffffu, ff[q], off);
        #pragma unroll
        for (int q = 0; q < NIQ; q++) ii[q] += __shfl_down_sync(0xffffffffu, ii[q], off);
    }
    if (lane == 0) {
        int nGT = ii[4];
        float nM = (float)ii[1];
        float lx = ff[0] / nM, ly = ff[1] / nM, lw = ff[2] / nM, lh = ff[3] / nM;
        float coord = lx + ly + lw + lh;
        float cmfB = ff[8] - ff[6] - ff[7];
        float cmfC = (float)(NALL - ii[0]);
        float lconf = cmfB / cmfC + ff[5] / nM;
        float lcls  = (1.0f / NBATCH) * ff[4] / nM;
        float loss  = coord + lconf + lcls;
        float nCor  = (float)ii[3];
        int   gtd   = nGT > 1 ? nGT : 1;
        float recall = nCor / (float)gtd;
        float nProp = (float)ii[2];
        float prec  = (nProp > 0.f) ? (nCor / fmaxf(nProp, 1.f)) : 1.f;
        if (out_size >= 6) {
            out[0] = loss; out[1] = coord; out[2] = lconf;
            out[3] = lcls; out[4] = recall; out[5] = prec;
        }
    }
}

extern "C" void kernel_launch(void* const* d_in, const int* in_sizes, int n_in,
                              void* d_out, int out_size) {
    const float* pred = (const float*)d_in[0];
    const float* tgt  = (const float*)d_in[1];
    const int*   ts   = (const int*)d_in[2];
    float* out = (float*)d_out;

    k_mega<<<CONF_GRID, CONF_BLOCK>>>(pred, tgt, ts);
    k_tail<<<TAIL_GRID, TAIL_BLOCK>>>(pred, ts, out, out_size);
}